// round 14
// baseline (speedup 1.0000x reference)
#include <cuda_runtime.h>
#include <cuda_fp16.h>
#include <cstdint>

#define S_DIM 4096
#define H_DIM 1024
#define B_DIM 4

// ---------------- scratch (__device__ globals; no allocs allowed) -----------
__device__ __half g_xhi [B_DIM * S_DIM * H_DIM];
__device__ __half g_xThi[B_DIM * H_DIM * S_DIM];
__device__ __half g_WThi[H_DIM * H_DIM];
__device__ __half g_Ghi [B_DIM * H_DIM * H_DIM];
__device__ __half g_MThi[B_DIM * H_DIM * H_DIM];
__device__ float  g_P   [2 * B_DIM * 36 * 128 * 128];   // split-K partials

// ---------------- helpers ----------------------------------------------------
__device__ __forceinline__ uint32_t smem_u32(const void* p) {
    uint32_t a;
    asm("{ .reg .u64 t; cvta.to.shared.u64 t, %1; cvt.u32.u64 %0, t; }"
        : "=r"(a) : "l"(p));
    return a;
}

#define SWZ128(off) ((off) ^ (((off) >> 3) & 0x70))

__device__ __forceinline__ void cp_async16(uint32_t dst, const void* src) {
    asm volatile("cp.async.cg.shared.global [%0], [%1], 16;" :: "r"(dst), "l"(src));
}

__device__ __forceinline__ void ldsm4(uint32_t* r, uint32_t addr) {
    asm volatile("ldmatrix.sync.aligned.m8n8.x4.shared.b16 {%0,%1,%2,%3}, [%4];"
                 : "=r"(r[0]), "=r"(r[1]), "=r"(r[2]), "=r"(r[3]) : "r"(addr));
}

__device__ __forceinline__ void mma_f16(float* d, const uint32_t* a,
                                        uint32_t b0, uint32_t b1) {
    asm volatile(
        "mma.sync.aligned.m16n8k16.row.col.f32.f16.f16.f32 "
        "{%0,%1,%2,%3}, {%4,%5,%6,%7}, {%8,%9}, {%0,%1,%2,%3};"
        : "+f"(d[0]), "+f"(d[1]), "+f"(d[2]), "+f"(d[3])
        : "r"(a[0]), "r"(a[1]), "r"(a[2]), "r"(a[3]), "r"(b0), "r"(b1));
}

// ---------------- conversion kernels ----------------------------------------
// x: natural hi [R][C] + transposed hi [C][R].  64x64 tiles, 256 threads.
__global__ void x_conv_kernel(const float* __restrict__ in,
                              __half* __restrict__ hiN,
                              __half* __restrict__ hiT,
                              int R, int C) {
    __shared__ float tile[64][65];
    long boff = (long)blockIdx.z * R * C;
    int bx = blockIdx.x * 64;
    int by = blockIdx.y * 64;
    int tid = threadIdx.x;

#pragma unroll
    for (int i = 0; i < 4; ++i) {
        int j = tid + i * 256;        // float4 id 0..1023
        int row = j >> 4;             // 16 float4 per 64-col row
        int c4 = (j & 15) * 4;
        const float* sp = &in[boff + (long)(by + row) * C + bx + c4];
        float4 v = *reinterpret_cast<const float4*>(sp);
        tile[row][c4 + 0] = v.x;
        tile[row][c4 + 1] = v.y;
        tile[row][c4 + 2] = v.z;
        tile[row][c4 + 3] = v.w;
        __half* dp = &hiN[boff + (long)(by + row) * C + bx + c4];
        *reinterpret_cast<__half2*>(dp)     = __half2(__float2half_rn(v.x), __float2half_rn(v.y));
        *reinterpret_cast<__half2*>(dp + 2) = __half2(__float2half_rn(v.z), __float2half_rn(v.w));
    }
    __syncthreads();

    int l = tid & 31, w = tid >> 5;   // 8 warps x 8 cols each
#pragma unroll
    for (int i = 0; i < 8; ++i) {
        int oc = w * 8 + i;
        float v0 = tile[2 * l][oc];
        float v1 = tile[2 * l + 1][oc];
        __half2 hv(__float2half_rn(v0), __float2half_rn(v1));
        *reinterpret_cast<__half2*>(&hiT[boff + (long)(bx + oc) * R + by + 2 * l]) = hv;
    }
}

// W: transposed hi only, pre-scaled (x4096 keeps fp16 normal).
__global__ void w_conv_kernel(const float* __restrict__ in,
                              __half* __restrict__ hiT, int R, int C, float sc) {
    __shared__ float tile[32][33];
    int bx = blockIdx.x * 32;
    int by = blockIdx.y * 32;
    int tx = threadIdx.x, ty = threadIdx.y;
#pragma unroll
    for (int j = 0; j < 4; ++j)
        tile[ty + j * 8][tx] = in[(long)(by + ty + j * 8) * C + bx + tx];
    __syncthreads();
#pragma unroll
    for (int j = 0; j < 4; ++j) {
        int oc = bx + ty + j * 8;
        int orow = by + tx;
        hiT[(long)oc * R + orow] = __float2half_rn(tile[tx][ty + j * 8] * sc);
    }
}

// ---------------- HMMA GEMM ---------------------------------------------------
// C = P0 . PB^T, single fp16 operands, 3-stage cp.async, 2 CTA/SM, 8 warps 2x4.
// CTA tile 128x128, KTILE=64 fp16 (128B rows, SW128).
// MODE 0: fp32 C.  MODE 1: fp16 C.
// MODE 3: fp32 partial to tile-contiguous buffer; tri-block map; blockIdx.y = K-half.

#define KTILE 64
#define TILE_B 16384                 // 128 rows * 128 B
#define STAGE_B (2 * TILE_B)         // A, B
#define SMEM_TOT (3 * STAGE_B)       // 96 KB

template <int MODE>
__global__ __launch_bounds__(256, 2) void gemm_hmma(
    const __half* __restrict__ P0, const __half* __restrict__ PB,
    float* __restrict__ C, __half* __restrict__ Ch,
    int K, int lda, int ldb, int ldc,
    long s0, long sB, long sC, float cscale)
{
    extern __shared__ __align__(1024) unsigned char smem[];
    const uint32_t sbase = smem_u32(smem);
    const int tid = threadIdx.x;
    const int wid = tid >> 5;
    const int lane = tid & 31;
    const int warp_m = wid >> 2;
    const int warp_n = wid & 3;
    const int bz = blockIdx.z;

    int m0, n0, bi = 0, bj = 0;
    if (MODE == 3) {
        int r = blockIdx.x;
        while (r >= 8 - bi) { r -= 8 - bi; ++bi; }
        bj = bi + r;
        m0 = bi * 128; n0 = bj * 128;
    } else {
        m0 = blockIdx.y * 128; n0 = blockIdx.x * 128;
    }

    long koff = (MODE == 3) ? (long)blockIdx.y * K : 0L;
    const __half* srcA = P0 + bz * s0 + (long)m0 * lda + koff;
    const __half* srcB = PB + bz * sB + (long)n0 * ldb + koff;

    const int lr = lane & 7;
    const int lg = (lane >> 3) & 1;
    const int lk = (lane >> 4) & 1;
    const int arow = warp_m * 64 + lr + lg * 8;
    const int brow = warp_n * 32 + lr + lg * 8;
    const int colb0 = lk * 16;

    float acc[4][4][4];
#pragma unroll
    for (int i = 0; i < 4; ++i)
#pragma unroll
        for (int j = 0; j < 4; ++j)
#pragma unroll
            for (int c = 0; c < 4; ++c) acc[i][j][c] = 0.0f;

    const int T = K / KTILE;

    auto load_tile = [&](int p, int k0) {
        uint32_t dst0 = sbase + (uint32_t)p * STAGE_B;
#pragma unroll
        for (int i = 0; i < 8; ++i) {
            int cid = tid + i * 256;      // 0..2047
            int idx = cid & 1023;
            int row = idx >> 3;
            int ck = idx & 7;
            uint32_t off = (uint32_t)(row * 128 + ck * 16);
            if (cid < 1024) {
                cp_async16(dst0 + SWZ128(off), srcA + (long)row * lda + k0 + ck * 8);
            } else {
                cp_async16(dst0 + TILE_B + SWZ128(off), srcB + (long)row * ldb + k0 + ck * 8);
            }
        }
        asm volatile("cp.async.commit_group;");
    };

    load_tile(0, 0);
    if (T > 1) load_tile(1, KTILE);

    for (int t = 0; t < T; ++t) {
        if (t + 1 < T) asm volatile("cp.async.wait_group 1;");
        else           asm volatile("cp.async.wait_group 0;");
        __syncthreads();
        if (t + 2 < T) load_tile((t + 2) % 3, (t + 2) * KTILE);

        const uint32_t st = sbase + (uint32_t)(t % 3) * STAGE_B;
        const uint32_t ta = st;
        const uint32_t tb = st + TILE_B;

#pragma unroll
        for (int kk = 0; kk < KTILE; kk += 16) {
            const int colb = colb0 + kk * 2;
            uint32_t a[4][4], bf[2][4];
#pragma unroll
            for (int j = 0; j < 2; ++j) {
                uint32_t off = (uint32_t)((brow + j * 16) * 128 + colb);
                ldsm4(bf[j], tb + SWZ128(off));
            }
#pragma unroll
            for (int mi = 0; mi < 4; ++mi) {
                uint32_t off = (uint32_t)((arow + mi * 16) * 128 + colb);
                ldsm4(a[mi], ta + SWZ128(off));
            }
#pragma unroll
            for (int mi = 0; mi < 4; ++mi)
#pragma unroll
                for (int nj = 0; nj < 4; ++nj)
                    mma_f16(acc[mi][nj], a[mi], bf[nj >> 1][nj & 1], bf[nj >> 1][2 + (nj & 1)]);
        }
    }

    // ---------------- epilogue ----------------
    const int r = lane >> 2;
    const int c = (lane & 3) * 2;
    const int mb = m0 + warp_m * 64;
    const int nb = n0 + warp_n * 32;

    float* cpart = nullptr;
    if (MODE == 3)
        cpart = C + ((((long)blockIdx.y * gridDim.z) + bz) * 36 + blockIdx.x) * 16384;

#pragma unroll
    for (int mi = 0; mi < 4; ++mi)
#pragma unroll
        for (int nj = 0; nj < 4; ++nj) {
            int row = mb + mi * 16 + r;
            int col = nb + nj * 8 + c;
            float d0 = acc[mi][nj][0] * cscale, d1 = acc[mi][nj][1] * cscale;
            float d2 = acc[mi][nj][2] * cscale, d3 = acc[mi][nj][3] * cscale;
            if (MODE == 0) {
                float* cp = C + bz * sC + (long)row * ldc + col;
                *reinterpret_cast<float2*>(cp) = make_float2(d0, d1);
                float* cp2 = C + bz * sC + (long)(row + 8) * ldc + col;
                *reinterpret_cast<float2*>(cp2) = make_float2(d2, d3);
            } else if (MODE == 1) {
                long o0 = bz * sC + (long)row * ldc + col;
                long o1 = bz * sC + (long)(row + 8) * ldc + col;
                *reinterpret_cast<__half2*>(Ch + o0) =
                    __half2(__float2half_rn(d0), __float2half_rn(d1));
                *reinterpret_cast<__half2*>(Ch + o1) =
                    __half2(__float2half_rn(d2), __float2half_rn(d3));
            } else {  // MODE 3: fp32 partial, tile-local layout
                int lrow = row - m0, lcol = col - n0;
                *reinterpret_cast<float2*>(cpart + lrow * 128 + lcol) = make_float2(d0, d1);
                *reinterpret_cast<float2*>(cpart + (lrow + 8) * 128 + lcol) = make_float2(d2, d3);
            }
        }
}

// ---------------- combine: sum split-K partials, fp16, write + mirror --------
__global__ __launch_bounds__(256) void combine_g(
    const float* __restrict__ P, __half* __restrict__ G, int ldc, long sC, int B)
{
    __shared__ unsigned short tb[128 * 130];
    int t = blockIdx.x, bz = blockIdx.y;
    int bi = 0, r = t;
    while (r >= 8 - bi) { r -= 8 - bi; ++bi; }
    int bj = bi + r;
    int m0 = bi * 128, n0 = bj * 128;

    const float* A0 = P + ((long)bz * 36 + t) * 16384;
    const float* A1 = P + (((long)B + bz) * 36 + t) * 16384;
    int tid = threadIdx.x;

    for (int i = tid; i < 8192; i += 256) {
        int idx = i * 2;
        float2 a0 = reinterpret_cast<const float2*>(A0)[i];
        float2 a1 = reinterpret_cast<const float2*>(A1)[i];
        __half h0 = __float2half_rn(a0.x + a1.x);
        __half h1 = __float2half_rn(a0.y + a1.y);
        int row = idx >> 7, col = idx & 127;
        *reinterpret_cast<__half2*>(&G[bz * sC + (long)(m0 + row) * ldc + n0 + col]) =
            __half2(h0, h1);
        tb[row * 130 + col] = __half_as_ushort(h0);
        tb[row * 130 + col + 1] = __half_as_ushort(h1);
    }

    if (bi < bj) {
        __syncthreads();
        for (int j = tid; j < 8192; j += 256) {
            int rp = j >> 6;
            int cp2 = (j & 63) << 1;
            __half2 hv(__ushort_as_half(tb[cp2 * 130 + rp]),
                       __ushort_as_half(tb[(cp2 + 1) * 130 + rp]));
            long o = bz * sC + (long)(n0 + rp) * ldc + (m0 + cp2);
            *reinterpret_cast<__half2*>(&G[o]) = hv;
        }
    }
}

// ---------------- launch -----------------------------------------------------
extern "C" void kernel_launch(void* const* d_in, const int* in_sizes, int n_in,
                              void* d_out, int out_size) {
    const float* x = (const float*)d_in[0];
    const float* W = (const float*)d_in[1];
    float* out = (float*)d_out;

    const int S = S_DIM, H = H_DIM, B = B_DIM;
    const long HS = (long)H * S, HH = (long)H * H, SH = (long)S * H;

    __half *xhi, *xThi, *WThi, *Ghi, *MThi;
    float* Pbuf;
    cudaGetSymbolAddress((void**)&xhi, g_xhi);
    cudaGetSymbolAddress((void**)&xThi, g_xThi);
    cudaGetSymbolAddress((void**)&WThi, g_WThi);
    cudaGetSymbolAddress((void**)&Ghi, g_Ghi);
    cudaGetSymbolAddress((void**)&MThi, g_MThi);
    cudaGetSymbolAddress((void**)&Pbuf, g_P);

    cudaFuncSetAttribute(gemm_hmma<0>, cudaFuncAttributeMaxDynamicSharedMemorySize, SMEM_TOT);
    cudaFuncSetAttribute(gemm_hmma<1>, cudaFuncAttributeMaxDynamicSharedMemorySize, SMEM_TOT);
    cudaFuncSetAttribute(gemm_hmma<3>, cudaFuncAttributeMaxDynamicSharedMemorySize, SMEM_TOT);

    // conversions
    x_conv_kernel<<<dim3(H / 64, S / 64, B), 256>>>(x, xhi, xThi, S, H);
    w_conv_kernel<<<dim3(H / 32, H / 32, 1), dim3(32, 8)>>>(W, WThi, H, H, 4096.0f);

    // GEMM1 (symmetric, split-K x2): partials = xThi . xThi^T over K halves
    gemm_hmma<3><<<dim3(36, 2, B), 256, SMEM_TOT>>>(
        xThi, xThi, Pbuf, nullptr,
        S / 2, S, S, 128, HS, HS, 0L, 1.0f);

    // combine partials -> G (fp16, both triangles)
    combine_g<<<dim3(36, B), 256>>>(Pbuf, Ghi, H, HH, B);

    // GEMM2: MT[h][k] = G[h][.] . WT[k][.]^T ; carries W's x4096 scale
    gemm_hmma<1><<<dim3(8, 8, B), 256, SMEM_TOT>>>(
        Ghi, WThi, nullptr, MThi,
        H, H, H, H, HH, 0L, HH, 1.0f);

    // GEMM3: out = xhi . MT^T ; undo x4096
    gemm_hmma<0><<<dim3(8, 32, B), 256, SMEM_TOT>>>(
        xhi, MThi, out, nullptr,
        H, H, H, H, SH, HH, SH, 1.0f / 4096.0f);
}

// round 15
// speedup vs baseline: 1.0277x; 1.0277x over previous
#include <cuda_runtime.h>
#include <cuda_fp16.h>
#include <cstdint>

#define S_DIM 4096
#define H_DIM 1024
#define B_DIM 4

// ---------------- scratch (__device__ globals; no allocs allowed) -----------
__device__ __half g_xhi [B_DIM * S_DIM * H_DIM];
__device__ __half g_xThi[B_DIM * H_DIM * S_DIM];
__device__ __half g_WThi[H_DIM * H_DIM];
__device__ __half g_Ghi [B_DIM * H_DIM * H_DIM];
__device__ __half g_MThi[B_DIM * H_DIM * H_DIM];
__device__ float  g_P   [2 * B_DIM * 36 * 128 * 128];   // split-K partials

// ---------------- helpers ----------------------------------------------------
__device__ __forceinline__ uint32_t smem_u32(const void* p) {
    uint32_t a;
    asm("{ .reg .u64 t; cvta.to.shared.u64 t, %1; cvt.u32.u64 %0, t; }"
        : "=r"(a) : "l"(p));
    return a;
}

#define SWZ128(off) ((off) ^ (((off) >> 3) & 0x70))

__device__ __forceinline__ void cp_async16(uint32_t dst, const void* src) {
    asm volatile("cp.async.cg.shared.global [%0], [%1], 16;" :: "r"(dst), "l"(src));
}

__device__ __forceinline__ void ldsm4(uint32_t* r, uint32_t addr) {
    asm volatile("ldmatrix.sync.aligned.m8n8.x4.shared.b16 {%0,%1,%2,%3}, [%4];"
                 : "=r"(r[0]), "=r"(r[1]), "=r"(r[2]), "=r"(r[3]) : "r"(addr));
}

__device__ __forceinline__ void mma_f16(float* d, const uint32_t* a,
                                        uint32_t b0, uint32_t b1) {
    asm volatile(
        "mma.sync.aligned.m16n8k16.row.col.f32.f16.f16.f32 "
        "{%0,%1,%2,%3}, {%4,%5,%6,%7}, {%8,%9}, {%0,%1,%2,%3};"
        : "+f"(d[0]), "+f"(d[1]), "+f"(d[2]), "+f"(d[3])
        : "r"(a[0]), "r"(a[1]), "r"(a[2]), "r"(a[3]), "r"(b0), "r"(b1));
}

// ---------------- conversion kernels ----------------------------------------
// x: natural hi [R][C] + transposed hi [C][R].  64x64 tiles, 256 threads.
__global__ void x_conv_kernel(const float* __restrict__ in,
                              __half* __restrict__ hiN,
                              __half* __restrict__ hiT,
                              int R, int C) {
    __shared__ float tile[64][65];
    long boff = (long)blockIdx.z * R * C;
    int bx = blockIdx.x * 64;
    int by = blockIdx.y * 64;
    int tid = threadIdx.x;

#pragma unroll
    for (int i = 0; i < 4; ++i) {
        int j = tid + i * 256;        // float4 id 0..1023
        int row = j >> 4;             // 16 float4 per 64-col row
        int c4 = (j & 15) * 4;
        const float* sp = &in[boff + (long)(by + row) * C + bx + c4];
        float4 v = *reinterpret_cast<const float4*>(sp);
        tile[row][c4 + 0] = v.x;
        tile[row][c4 + 1] = v.y;
        tile[row][c4 + 2] = v.z;
        tile[row][c4 + 3] = v.w;
        __half* dp = &hiN[boff + (long)(by + row) * C + bx + c4];
        *reinterpret_cast<__half2*>(dp)     = __half2(__float2half_rn(v.x), __float2half_rn(v.y));
        *reinterpret_cast<__half2*>(dp + 2) = __half2(__float2half_rn(v.z), __float2half_rn(v.w));
    }
    __syncthreads();

    int l = tid & 31, w = tid >> 5;   // 8 warps x 8 cols each
#pragma unroll
    for (int i = 0; i < 8; ++i) {
        int oc = w * 8 + i;
        float v0 = tile[2 * l][oc];
        float v1 = tile[2 * l + 1][oc];
        __half2 hv(__float2half_rn(v0), __float2half_rn(v1));
        *reinterpret_cast<__half2*>(&hiT[boff + (long)(bx + oc) * R + by + 2 * l]) = hv;
    }
}

// W: transposed hi only, pre-scaled (x4096 keeps fp16 normal).
__global__ void w_conv_kernel(const float* __restrict__ in,
                              __half* __restrict__ hiT, int R, int C, float sc) {
    __shared__ float tile[32][33];
    int bx = blockIdx.x * 32;
    int by = blockIdx.y * 32;
    int tx = threadIdx.x, ty = threadIdx.y;
#pragma unroll
    for (int j = 0; j < 4; ++j)
        tile[ty + j * 8][tx] = in[(long)(by + ty + j * 8) * C + bx + tx];
    __syncthreads();
#pragma unroll
    for (int j = 0; j < 4; ++j) {
        int oc = bx + ty + j * 8;
        int orow = by + tx;
        hiT[(long)oc * R + orow] = __float2half_rn(tile[tx][ty + j * 8] * sc);
    }
}

// ---------------- HMMA GEMM ---------------------------------------------------
// C = P0 . PB^T, single fp16 operands, 3-stage cp.async, 2 CTA/SM, 8 warps 2x4.
// CTA tile 128x128, KTILE=64 fp16 (128B rows, SW128).
// MODE 0: fp32 C.  MODE 1: fp16 C.
// MODE 3: fp32 partial to tile-contiguous buffer; tri-block map; blockIdx.y = K-half.

#define KTILE 64
#define TILE_B 16384                 // 128 rows * 128 B
#define STAGE_B (2 * TILE_B)         // A, B
#define SMEM_TOT (3 * STAGE_B)       // 96 KB

template <int MODE>
__global__ __launch_bounds__(256, 2) void gemm_hmma(
    const __half* __restrict__ P0, const __half* __restrict__ PB,
    float* __restrict__ C, __half* __restrict__ Ch,
    int K, int lda, int ldb, int ldc,
    long s0, long sB, long sC, float cscale)
{
    extern __shared__ __align__(1024) unsigned char smem[];
    const uint32_t sbase = smem_u32(smem);
    const int tid = threadIdx.x;
    const int wid = tid >> 5;
    const int lane = tid & 31;
    const int warp_m = wid >> 2;
    const int warp_n = wid & 3;
    const int bz = blockIdx.z;

    int m0, n0, bi = 0, bj = 0;
    if (MODE == 3) {
        int r = blockIdx.x;
        while (r >= 8 - bi) { r -= 8 - bi; ++bi; }
        bj = bi + r;
        m0 = bi * 128; n0 = bj * 128;
    } else {
        m0 = blockIdx.y * 128; n0 = blockIdx.x * 128;
    }

    long koff = (MODE == 3) ? (long)blockIdx.y * K : 0L;
    const __half* srcA = P0 + bz * s0 + (long)m0 * lda + koff;
    const __half* srcB = PB + bz * sB + (long)n0 * ldb + koff;

    const int lr = lane & 7;
    const int lg = (lane >> 3) & 1;
    const int lk = (lane >> 4) & 1;
    const int arow = warp_m * 64 + lr + lg * 8;
    const int brow = warp_n * 32 + lr + lg * 8;
    const int colb0 = lk * 16;

    float acc[4][4][4];
#pragma unroll
    for (int i = 0; i < 4; ++i)
#pragma unroll
        for (int j = 0; j < 4; ++j)
#pragma unroll
            for (int c = 0; c < 4; ++c) acc[i][j][c] = 0.0f;

    const int T = K / KTILE;

    auto load_tile = [&](int p, int k0) {
        uint32_t dst0 = sbase + (uint32_t)p * STAGE_B;
#pragma unroll
        for (int i = 0; i < 8; ++i) {
            int cid = tid + i * 256;      // 0..2047
            int idx = cid & 1023;
            int row = idx >> 3;
            int ck = idx & 7;
            uint32_t off = (uint32_t)(row * 128 + ck * 16);
            if (cid < 1024) {
                cp_async16(dst0 + SWZ128(off), srcA + (long)row * lda + k0 + ck * 8);
            } else {
                cp_async16(dst0 + TILE_B + SWZ128(off), srcB + (long)row * ldb + k0 + ck * 8);
            }
        }
        asm volatile("cp.async.commit_group;");
    };

    load_tile(0, 0);
    if (T > 1) load_tile(1, KTILE);

    for (int t = 0; t < T; ++t) {
        if (t + 1 < T) asm volatile("cp.async.wait_group 1;");
        else           asm volatile("cp.async.wait_group 0;");
        __syncthreads();
        if (t + 2 < T) load_tile((t + 2) % 3, (t + 2) * KTILE);

        const uint32_t st = sbase + (uint32_t)(t % 3) * STAGE_B;
        const uint32_t ta = st;
        const uint32_t tb = st + TILE_B;

#pragma unroll
        for (int kk = 0; kk < KTILE; kk += 16) {
            const int colb = colb0 + kk * 2;
            uint32_t a[4][4], bf[2][4];
#pragma unroll
            for (int j = 0; j < 2; ++j) {
                uint32_t off = (uint32_t)((brow + j * 16) * 128 + colb);
                ldsm4(bf[j], tb + SWZ128(off));
            }
#pragma unroll
            for (int mi = 0; mi < 4; ++mi) {
                uint32_t off = (uint32_t)((arow + mi * 16) * 128 + colb);
                ldsm4(a[mi], ta + SWZ128(off));
            }
#pragma unroll
            for (int mi = 0; mi < 4; ++mi)
#pragma unroll
                for (int nj = 0; nj < 4; ++nj)
                    mma_f16(acc[mi][nj], a[mi], bf[nj >> 1][nj & 1], bf[nj >> 1][2 + (nj & 1)]);
        }
    }

    // ---------------- epilogue ----------------
    const int r = lane >> 2;
    const int c = (lane & 3) * 2;
    const int mb = m0 + warp_m * 64;
    const int nb = n0 + warp_n * 32;

    float* cpart = nullptr;
    if (MODE == 3)
        cpart = C + ((((long)blockIdx.y * gridDim.z) + bz) * 36 + blockIdx.x) * 16384;

#pragma unroll
    for (int mi = 0; mi < 4; ++mi)
#pragma unroll
        for (int nj = 0; nj < 4; ++nj) {
            int row = mb + mi * 16 + r;
            int col = nb + nj * 8 + c;
            float d0 = acc[mi][nj][0] * cscale, d1 = acc[mi][nj][1] * cscale;
            float d2 = acc[mi][nj][2] * cscale, d3 = acc[mi][nj][3] * cscale;
            if (MODE == 0) {
                float* cp = C + bz * sC + (long)row * ldc + col;
                *reinterpret_cast<float2*>(cp) = make_float2(d0, d1);
                float* cp2 = C + bz * sC + (long)(row + 8) * ldc + col;
                *reinterpret_cast<float2*>(cp2) = make_float2(d2, d3);
            } else if (MODE == 1) {
                long o0 = bz * sC + (long)row * ldc + col;
                long o1 = bz * sC + (long)(row + 8) * ldc + col;
                *reinterpret_cast<__half2*>(Ch + o0) =
                    __half2(__float2half_rn(d0), __float2half_rn(d1));
                *reinterpret_cast<__half2*>(Ch + o1) =
                    __half2(__float2half_rn(d2), __float2half_rn(d3));
            } else {  // MODE 3: fp32 partial, tile-local layout
                int lrow = row - m0, lcol = col - n0;
                *reinterpret_cast<float2*>(cpart + lrow * 128 + lcol) = make_float2(d0, d1);
                *reinterpret_cast<float2*>(cpart + (lrow + 8) * 128 + lcol) = make_float2(d2, d3);
            }
        }
}

// ---------------- combine: sum split-K partials, fp16, write + mirror --------
// grid (36, 4, B): each CTA handles a 32-row chunk of one 128x128 tile.
__global__ __launch_bounds__(256) void combine_g(
    const float* __restrict__ P, __half* __restrict__ G, int ldc, long sC, int B)
{
    __shared__ unsigned short tb[32 * 130];
    int t = blockIdx.x, ch = blockIdx.y, bz = blockIdx.z;
    int bi = 0, r = t;
    while (r >= 8 - bi) { r -= 8 - bi; ++bi; }
    int bj = bi + r;
    int m0 = bi * 128, n0 = bj * 128;
    int r0 = ch * 32;                  // tile-local row offset of this chunk

    const float* A0 = P + ((long)bz * 36 + t) * 16384 + r0 * 128;
    const float* A1 = P + (((long)B + bz) * 36 + t) * 16384 + r0 * 128;
    int tid = threadIdx.x;

    // 32 rows x 128 cols = 4096 floats = 2048 float2; 256 threads x 8 iters
#pragma unroll
    for (int i = 0; i < 8; ++i) {
        int j = tid + i * 256;         // float2 index 0..2047
        float2 a0 = reinterpret_cast<const float2*>(A0)[j];
        float2 a1 = reinterpret_cast<const float2*>(A1)[j];
        __half h0 = __float2half_rn(a0.x + a1.x);
        __half h1 = __float2half_rn(a0.y + a1.y);
        int row = j >> 6;              // 64 float2 per row
        int col = (j & 63) << 1;
        *reinterpret_cast<__half2*>(
            &G[bz * sC + (long)(m0 + r0 + row) * ldc + n0 + col]) = __half2(h0, h1);
        tb[row * 130 + col] = __half_as_ushort(h0);
        tb[row * 130 + col + 1] = __half_as_ushort(h1);
    }

    if (bi < bj) {
        __syncthreads();
        // mirror: G[n0+p][m0 + r0 + 2q] for p in 0..127, q in 0..15
#pragma unroll
        for (int i = 0; i < 8; ++i) {
            int j = tid + i * 256;     // 0..2047
            int p = j >> 4;            // 0..127
            int q2 = (j & 15) << 1;    // 0..30 step 2
            __half2 hv(__ushort_as_half(tb[q2 * 130 + p]),
                       __ushort_as_half(tb[(q2 + 1) * 130 + p]));
            long o = bz * sC + (long)(n0 + p) * ldc + (m0 + r0 + q2);
            *reinterpret_cast<__half2*>(&G[o]) = hv;
        }
    }
}

// ---------------- launch -----------------------------------------------------
extern "C" void kernel_launch(void* const* d_in, const int* in_sizes, int n_in,
                              void* d_out, int out_size) {
    const float* x = (const float*)d_in[0];
    const float* W = (const float*)d_in[1];
    float* out = (float*)d_out;

    const int S = S_DIM, H = H_DIM, B = B_DIM;
    const long HS = (long)H * S, HH = (long)H * H, SH = (long)S * H;

    __half *xhi, *xThi, *WThi, *Ghi, *MThi;
    float* Pbuf;
    cudaGetSymbolAddress((void**)&xhi, g_xhi);
    cudaGetSymbolAddress((void**)&xThi, g_xThi);
    cudaGetSymbolAddress((void**)&WThi, g_WThi);
    cudaGetSymbolAddress((void**)&Ghi, g_Ghi);
    cudaGetSymbolAddress((void**)&MThi, g_MThi);
    cudaGetSymbolAddress((void**)&Pbuf, g_P);

    cudaFuncSetAttribute(gemm_hmma<0>, cudaFuncAttributeMaxDynamicSharedMemorySize, SMEM_TOT);
    cudaFuncSetAttribute(gemm_hmma<1>, cudaFuncAttributeMaxDynamicSharedMemorySize, SMEM_TOT);
    cudaFuncSetAttribute(gemm_hmma<3>, cudaFuncAttributeMaxDynamicSharedMemorySize, SMEM_TOT);

    // conversions
    x_conv_kernel<<<dim3(H / 64, S / 64, B), 256>>>(x, xhi, xThi, S, H);
    w_conv_kernel<<<dim3(H / 32, H / 32, 1), dim3(32, 8)>>>(W, WThi, H, H, 4096.0f);

    // GEMM1 (symmetric, split-K x2): partials = xThi . xThi^T over K halves
    gemm_hmma<3><<<dim3(36, 2, B), 256, SMEM_TOT>>>(
        xThi, xThi, Pbuf, nullptr,
        S / 2, S, S, 128, HS, HS, 0L, 1.0f);

    // combine partials -> G (fp16, both triangles), 4 chunks per tile
    combine_g<<<dim3(36, 4, B), 256>>>(Pbuf, Ghi, H, HH, B);

    // GEMM2: MT[h][k] = G[h][.] . WT[k][.]^T ; carries W's x4096 scale
    gemm_hmma<1><<<dim3(8, 8, B), 256, SMEM_TOT>>>(
        Ghi, WThi, nullptr, MThi,
        H, H, H, H, HH, 0L, HH, 1.0f);

    // GEMM3: out = xhi . MT^T ; undo x4096
    gemm_hmma<0><<<dim3(8, 32, B), 256, SMEM_TOT>>>(
        xhi, MThi, out, nullptr,
        H, H, H, H, SH, HH, SH, 1.0f / 4096.0f);
}

// round 16
// speedup vs baseline: 1.0354x; 1.0075x over previous
#include <cuda_runtime.h>
#include <cuda_fp16.h>
#include <cstdint>

#define S_DIM 4096
#define H_DIM 1024
#define B_DIM 4

// ---------------- scratch (__device__ globals; no allocs allowed) -----------
__device__ __half g_xhi [B_DIM * S_DIM * H_DIM];
__device__ __half g_WThi[H_DIM * H_DIM];
__device__ __half g_Ghi [B_DIM * H_DIM * H_DIM];
__device__ __half g_MThi[B_DIM * H_DIM * H_DIM];
__device__ float  g_P   [2 * B_DIM * 36 * 128 * 128];   // split-K partials

// ---------------- helpers ----------------------------------------------------
__device__ __forceinline__ uint32_t smem_u32(const void* p) {
    uint32_t a;
    asm("{ .reg .u64 t; cvta.to.shared.u64 t, %1; cvt.u32.u64 %0, t; }"
        : "=r"(a) : "l"(p));
    return a;
}

#define SWZ128(off) ((off) ^ (((off) >> 3) & 0x70))

__device__ __forceinline__ void cp_async16(uint32_t dst, const void* src) {
    asm volatile("cp.async.cg.shared.global [%0], [%1], 16;" :: "r"(dst), "l"(src));
}

__device__ __forceinline__ void ldsm4(uint32_t* r, uint32_t addr) {
    asm volatile("ldmatrix.sync.aligned.m8n8.x4.shared.b16 {%0,%1,%2,%3}, [%4];"
                 : "=r"(r[0]), "=r"(r[1]), "=r"(r[2]), "=r"(r[3]) : "r"(addr));
}

__device__ __forceinline__ void ldsm4t(uint32_t* r, uint32_t addr) {
    asm volatile("ldmatrix.sync.aligned.m8n8.x4.trans.shared.b16 {%0,%1,%2,%3}, [%4];"
                 : "=r"(r[0]), "=r"(r[1]), "=r"(r[2]), "=r"(r[3]) : "r"(addr));
}

__device__ __forceinline__ void mma_f16(float* d, const uint32_t* a,
                                        uint32_t b0, uint32_t b1) {
    asm volatile(
        "mma.sync.aligned.m16n8k16.row.col.f32.f16.f16.f32 "
        "{%0,%1,%2,%3}, {%4,%5,%6,%7}, {%8,%9}, {%0,%1,%2,%3};"
        : "+f"(d[0]), "+f"(d[1]), "+f"(d[2]), "+f"(d[3])
        : "r"(a[0]), "r"(a[1]), "r"(a[2]), "r"(a[3]), "r"(b0), "r"(b1));
}

// ---------------- conversion kernels ----------------------------------------
// x: pure streaming fp32 -> fp16 convert (natural layout only)
__global__ void x_split_kernel(const float* __restrict__ in,
                               __half* __restrict__ out) {
    int i = blockIdx.x * blockDim.x + threadIdx.x;
    float4 v = reinterpret_cast<const float4*>(in)[i];
    reinterpret_cast<__half2*>(out)[2 * i] =
        __half2(__float2half_rn(v.x), __float2half_rn(v.y));
    reinterpret_cast<__half2*>(out)[2 * i + 1] =
        __half2(__float2half_rn(v.z), __float2half_rn(v.w));
}

// W: transposed hi only, pre-scaled (x4096 keeps fp16 normal).
__global__ void w_conv_kernel(const float* __restrict__ in,
                              __half* __restrict__ hiT, int R, int C, float sc) {
    __shared__ float tile[32][33];
    int bx = blockIdx.x * 32;
    int by = blockIdx.y * 32;
    int tx = threadIdx.x, ty = threadIdx.y;
#pragma unroll
    for (int j = 0; j < 4; ++j)
        tile[ty + j * 8][tx] = in[(long)(by + ty + j * 8) * C + bx + tx];
    __syncthreads();
#pragma unroll
    for (int j = 0; j < 4; ++j) {
        int oc = bx + ty + j * 8;
        int orow = by + tx;
        hiT[(long)oc * R + orow] = __float2half_rn(tile[tx][ty + j * 8] * sc);
    }
}

// ---------------- GEMM1: G-partial = x^T x from NATURAL-layout x -------------
// Fragments via ldmatrix.trans (stored [t][h] tiles). Tile = 64 t-rows x 256B,
// stored as two 128B-wide swizzle regions (cols 0-63, 64-127).
// grid (36 tri-blocks, 2 K-halves, B). fp32 partials, tile-contiguous.

#define KT1 64
#define T1_TILE 16384                 // 64 rows * 256 B
#define T1_STAGE (2 * T1_TILE)        // A, B
#define SMEM1_TOT (3 * T1_STAGE)      // 96 KB

__global__ __launch_bounds__(256, 2) void gemm_symt(
    const __half* __restrict__ X, float* __restrict__ P,
    int Khalf, int lda, long sX)
{
    extern __shared__ __align__(1024) unsigned char smem[];
    const uint32_t sbase = smem_u32(smem);
    const int tid = threadIdx.x;
    const int wid = tid >> 5;
    const int lane = tid & 31;
    const int warp_m = wid >> 2;
    const int warp_n = wid & 3;
    const int bz = blockIdx.z;

    int bi = 0, r = blockIdx.x;
    while (r >= 8 - bi) { r -= 8 - bi; ++bi; }
    int bj = bi + r;
    const int m0 = bi * 128, n0 = bj * 128;

    const long koff = (long)blockIdx.y * Khalf;
    const __half* src = X + bz * sX + koff * lda;

    // lane constants for trans-ldsm addressing
    const int l = lane & 7;
    const int j = lane >> 3;
    const uint32_t lrow = (uint32_t)((((j >> 1) * 8) + l) * 128);
    const uint32_t lmask = (uint32_t)(l << 4);
    uint32_t acol[4], bcol[2];
#pragma unroll
    for (int mi = 0; mi < 4; ++mi)
        acol[mi] = ((uint32_t)((mi * 16 + (j & 1) * 8) * 2)) ^ lmask;
#pragma unroll
    for (int u = 0; u < 2; ++u)
        bcol[u] = ((uint32_t)(((warp_n & 1) * 32 + u * 16 + (j & 1) * 8) * 2)) ^ lmask;
    const uint32_t aregion = (uint32_t)warp_m * 8192;
    const uint32_t bregion = (uint32_t)(warp_n >> 1) * 8192;

    float acc[4][4][4];
#pragma unroll
    for (int i = 0; i < 4; ++i)
#pragma unroll
        for (int q = 0; q < 4; ++q)
#pragma unroll
            for (int c = 0; c < 4; ++c) acc[i][q][c] = 0.0f;

    const int T = Khalf / KT1;

    auto load_tile = [&](int p, int k0) {
        uint32_t dst0 = sbase + (uint32_t)p * T1_STAGE;
#pragma unroll
        for (int i = 0; i < 8; ++i) {
            int cid = tid + i * 256;      // 0..2047
            int tile = cid >> 10;         // 0: A(m0 cols), 1: B(n0 cols)
            int idx = cid & 1023;
            int row = idx >> 4;           // t row 0..63
            int ck = idx & 15;            // 16B chunk 0..15 (128 cols)
            const __half* sp = src + (long)(k0 + row) * lda
                             + (tile ? n0 : m0) + ck * 8;
            uint32_t off = (uint32_t)((ck >> 3) * 8192)
                         + SWZ128((uint32_t)(row * 128 + (ck & 7) * 16));
            cp_async16(dst0 + (uint32_t)tile * T1_TILE + off, sp);
        }
        asm volatile("cp.async.commit_group;");
    };

    load_tile(0, 0);
    if (T > 1) load_tile(1, KT1);

    for (int t = 0; t < T; ++t) {
        if (t + 1 < T) asm volatile("cp.async.wait_group 1;");
        else           asm volatile("cp.async.wait_group 0;");
        __syncthreads();
        if (t + 2 < T) load_tile((t + 2) % 3, (t + 2) * KT1);

        const uint32_t st = sbase + (uint32_t)(t % 3) * T1_STAGE;
        const uint32_t ta = st + aregion;
        const uint32_t tb = st + T1_TILE + bregion;

#pragma unroll
        for (int kk = 0; kk < KT1; kk += 16) {
            const uint32_t kbase = (uint32_t)(kk * 128) + lrow;
            uint32_t a[4][4], bf[2][4];
#pragma unroll
            for (int u = 0; u < 2; ++u)
                ldsm4t(bf[u], tb + kbase + bcol[u]);
#pragma unroll
            for (int mi = 0; mi < 4; ++mi)
                ldsm4t(a[mi], ta + kbase + acol[mi]);
#pragma unroll
            for (int mi = 0; mi < 4; ++mi)
#pragma unroll
                for (int nj = 0; nj < 4; ++nj)
                    mma_f16(acc[mi][nj], a[mi], bf[nj >> 1][nj & 1], bf[nj >> 1][2 + (nj & 1)]);
        }
    }

    // epilogue: fp32 partial, tile-local layout
    const int rr = lane >> 2;
    const int cc = (lane & 3) * 2;
    float* cpart = P + ((((long)blockIdx.y * gridDim.z) + bz) * 36 + blockIdx.x) * 16384;

#pragma unroll
    for (int mi = 0; mi < 4; ++mi)
#pragma unroll
        for (int nj = 0; nj < 4; ++nj) {
            int lrow0 = warp_m * 64 + mi * 16 + rr;
            int lcol = warp_n * 32 + nj * 8 + cc;
            *reinterpret_cast<float2*>(cpart + lrow0 * 128 + lcol) =
                make_float2(acc[mi][nj][0], acc[mi][nj][1]);
            *reinterpret_cast<float2*>(cpart + (lrow0 + 8) * 128 + lcol) =
                make_float2(acc[mi][nj][2], acc[mi][nj][3]);
        }
}

// ---------------- HMMA GEMM (K-major operands; GEMM2 + GEMM3) ----------------
// C = P0 . PB^T, single fp16 operands, 3-stage cp.async, 2 CTA/SM, 8 warps 2x4.
// MODE 0: fp32 C.  MODE 1: fp16 C.

#define KTILE 64
#define TILE_B 16384                 // 128 rows * 128 B
#define STAGE_B (2 * TILE_B)         // A, B
#define SMEM_TOT (3 * STAGE_B)       // 96 KB

template <int MODE>
__global__ __launch_bounds__(256, 2) void gemm_hmma(
    const __half* __restrict__ P0, const __half* __restrict__ PB,
    float* __restrict__ C, __half* __restrict__ Ch,
    int K, int lda, int ldb, int ldc,
    long s0, long sB, long sC, float cscale)
{
    extern __shared__ __align__(1024) unsigned char smem[];
    const uint32_t sbase = smem_u32(smem);
    const int tid = threadIdx.x;
    const int wid = tid >> 5;
    const int lane = tid & 31;
    const int warp_m = wid >> 2;
    const int warp_n = wid & 3;
    const int bz = blockIdx.z;
    const int m0 = blockIdx.y * 128;
    const int n0 = blockIdx.x * 128;

    const __half* srcA = P0 + bz * s0 + (long)m0 * lda;
    const __half* srcB = PB + bz * sB + (long)n0 * ldb;

    const int lr = lane & 7;
    const int lg = (lane >> 3) & 1;
    const int lk = (lane >> 4) & 1;
    const int arow = warp_m * 64 + lr + lg * 8;
    const int brow = warp_n * 32 + lr + lg * 8;
    const int colb0 = lk * 16;

    float acc[4][4][4];
#pragma unroll
    for (int i = 0; i < 4; ++i)
#pragma unroll
        for (int q = 0; q < 4; ++q)
#pragma unroll
            for (int c = 0; c < 4; ++c) acc[i][q][c] = 0.0f;

    const int T = K / KTILE;

    auto load_tile = [&](int p, int k0) {
        uint32_t dst0 = sbase + (uint32_t)p * STAGE_B;
#pragma unroll
        for (int i = 0; i < 8; ++i) {
            int cid = tid + i * 256;
            int idx = cid & 1023;
            int row = idx >> 3;
            int ck = idx & 7;
            uint32_t off = (uint32_t)(row * 128 + ck * 16);
            if (cid < 1024) {
                cp_async16(dst0 + SWZ128(off), srcA + (long)row * lda + k0 + ck * 8);
            } else {
                cp_async16(dst0 + TILE_B + SWZ128(off), srcB + (long)row * ldb + k0 + ck * 8);
            }
        }
        asm volatile("cp.async.commit_group;");
    };

    load_tile(0, 0);
    if (T > 1) load_tile(1, KTILE);

    for (int t = 0; t < T; ++t) {
        if (t + 1 < T) asm volatile("cp.async.wait_group 1;");
        else           asm volatile("cp.async.wait_group 0;");
        __syncthreads();
        if (t + 2 < T) load_tile((t + 2) % 3, (t + 2) * KTILE);

        const uint32_t st = sbase + (uint32_t)(t % 3) * STAGE_B;
        const uint32_t ta = st;
        const uint32_t tb = st + TILE_B;

#pragma unroll
        for (int kk = 0; kk < KTILE; kk += 16) {
            const int colb = colb0 + kk * 2;
            uint32_t a[4][4], bf[2][4];
#pragma unroll
            for (int q = 0; q < 2; ++q) {
                uint32_t off = (uint32_t)((brow + q * 16) * 128 + colb);
                ldsm4(bf[q], tb + SWZ128(off));
            }
#pragma unroll
            for (int mi = 0; mi < 4; ++mi) {
                uint32_t off = (uint32_t)((arow + mi * 16) * 128 + colb);
                ldsm4(a[mi], ta + SWZ128(off));
            }
#pragma unroll
            for (int mi = 0; mi < 4; ++mi)
#pragma unroll
                for (int nj = 0; nj < 4; ++nj)
                    mma_f16(acc[mi][nj], a[mi], bf[nj >> 1][nj & 1], bf[nj >> 1][2 + (nj & 1)]);
        }
    }

    const int rr = lane >> 2;
    const int cc = (lane & 3) * 2;
    const int mb = m0 + warp_m * 64;
    const int nb = n0 + warp_n * 32;

#pragma unroll
    for (int mi = 0; mi < 4; ++mi)
#pragma unroll
        for (int nj = 0; nj < 4; ++nj) {
            int row = mb + mi * 16 + rr;
            int col = nb + nj * 8 + cc;
            float d0 = acc[mi][nj][0] * cscale, d1 = acc[mi][nj][1] * cscale;
            float d2 = acc[mi][nj][2] * cscale, d3 = acc[mi][nj][3] * cscale;
            if (MODE == 0) {
                float* cp = C + bz * sC + (long)row * ldc + col;
                *reinterpret_cast<float2*>(cp) = make_float2(d0, d1);
                float* cp2 = C + bz * sC + (long)(row + 8) * ldc + col;
                *reinterpret_cast<float2*>(cp2) = make_float2(d2, d3);
            } else {
                long o0 = bz * sC + (long)row * ldc + col;
                long o1 = bz * sC + (long)(row + 8) * ldc + col;
                *reinterpret_cast<__half2*>(Ch + o0) =
                    __half2(__float2half_rn(d0), __float2half_rn(d1));
                *reinterpret_cast<__half2*>(Ch + o1) =
                    __half2(__float2half_rn(d2), __float2half_rn(d3));
            }
        }
}

// ---------------- combine: sum split-K partials, fp16, write + mirror --------
// grid (36, 4, B): each CTA handles a 32-row chunk of one 128x128 tile.
__global__ __launch_bounds__(256) void combine_g(
    const float* __restrict__ P, __half* __restrict__ G, int ldc, long sC, int B)
{
    __shared__ unsigned short tb[32 * 130];
    int t = blockIdx.x, ch = blockIdx.y, bz = blockIdx.z;
    int bi = 0, r = t;
    while (r >= 8 - bi) { r -= 8 - bi; ++bi; }
    int bj = bi + r;
    int m0 = bi * 128, n0 = bj * 128;
    int r0 = ch * 32;

    const float* A0 = P + ((long)bz * 36 + t) * 16384 + r0 * 128;
    const float* A1 = P + (((long)B + bz) * 36 + t) * 16384 + r0 * 128;
    int tid = threadIdx.x;

#pragma unroll
    for (int i = 0; i < 8; ++i) {
        int j = tid + i * 256;
        float2 a0 = reinterpret_cast<const float2*>(A0)[j];
        float2 a1 = reinterpret_cast<const float2*>(A1)[j];
        __half h0 = __float2half_rn(a0.x + a1.x);
        __half h1 = __float2half_rn(a0.y + a1.y);
        int row = j >> 6;
        int col = (j & 63) << 1;
        *reinterpret_cast<__half2*>(
            &G[bz * sC + (long)(m0 + r0 + row) * ldc + n0 + col]) = __half2(h0, h1);
        tb[row * 130 + col] = __half_as_ushort(h0);
        tb[row * 130 + col + 1] = __half_as_ushort(h1);
    }

    if (bi < bj) {
        __syncthreads();
#pragma unroll
        for (int i = 0; i < 8; ++i) {
            int j = tid + i * 256;
            int p = j >> 4;
            int q2 = (j & 15) << 1;
            __half2 hv(__ushort_as_half(tb[q2 * 130 + p]),
                       __ushort_as_half(tb[(q2 + 1) * 130 + p]));
            long o = bz * sC + (long)(n0 + p) * ldc + (m0 + r0 + q2);
            *reinterpret_cast<__half2*>(&G[o]) = hv;
        }
    }
}

// ---------------- launch -----------------------------------------------------
extern "C" void kernel_launch(void* const* d_in, const int* in_sizes, int n_in,
                              void* d_out, int out_size) {
    const float* x = (const float*)d_in[0];
    const float* W = (const float*)d_in[1];
    float* out = (float*)d_out;

    const int S = S_DIM, H = H_DIM, B = B_DIM;
    const long HH = (long)H * H, SH = (long)S * H;

    __half *xhi, *WThi, *Ghi, *MThi;
    float* Pbuf;
    cudaGetSymbolAddress((void**)&xhi, g_xhi);
    cudaGetSymbolAddress((void**)&WThi, g_WThi);
    cudaGetSymbolAddress((void**)&Ghi, g_Ghi);
    cudaGetSymbolAddress((void**)&MThi, g_MThi);
    cudaGetSymbolAddress((void**)&Pbuf, g_P);

    cudaFuncSetAttribute(gemm_hmma<0>, cudaFuncAttributeMaxDynamicSharedMemorySize, SMEM_TOT);
    cudaFuncSetAttribute(gemm_hmma<1>, cudaFuncAttributeMaxDynamicSharedMemorySize, SMEM_TOT);
    cudaFuncSetAttribute(gemm_symt, cudaFuncAttributeMaxDynamicSharedMemorySize, SMEM1_TOT);

    // conversions
    x_split_kernel<<<(B * S * H / 4 + 255) / 256, 256>>>(x, xhi);
    w_conv_kernel<<<dim3(H / 32, H / 32, 1), dim3(32, 8)>>>(W, WThi, H, H, 4096.0f);

    // GEMM1 (symmetric, split-K x2, natural-layout x via ldmatrix.trans)
    gemm_symt<<<dim3(36, 2, B), 256, SMEM1_TOT>>>(
        xhi, Pbuf, S / 2, H, SH);

    // combine partials -> G (fp16, both triangles), 4 chunks per tile
    combine_g<<<dim3(36, 4, B), 256>>>(Pbuf, Ghi, H, HH, B);

    // GEMM2: MT[h][k] = G[h][.] . WT[k][.]^T ; carries W's x4096 scale
    gemm_hmma<1><<<dim3(8, 8, B), 256, SMEM_TOT>>>(
        Ghi, WThi, nullptr, MThi,
        H, H, H, H, HH, 0L, HH, 1.0f);

    // GEMM3: out = xhi . MT^T ; undo x4096
    gemm_hmma<0><<<dim3(8, 32, B), 256, SMEM_TOT>>>(
        xhi, MThi, out, nullptr,
        H, H, H, H, SH, HH, SH, 1.0f / 4096.0f);
}

// round 17
// speedup vs baseline: 1.0361x; 1.0007x over previous
#include <cuda_runtime.h>
#include <cuda_fp16.h>
#include <cstdint>

#define S_DIM 4096
#define H_DIM 1024
#define B_DIM 4

// ---------------- scratch (__device__ globals; no allocs allowed) -----------
__device__ __half g_xhi [B_DIM * S_DIM * H_DIM];
__device__ __half g_WThi[H_DIM * H_DIM];
__device__ __half g_Ghi [B_DIM * H_DIM * H_DIM];
__device__ __half g_MThi[B_DIM * H_DIM * H_DIM];
__device__ float  g_P   [2 * B_DIM * 36 * 128 * 128];   // split-K partials

// ---------------- helpers ----------------------------------------------------
__device__ __forceinline__ uint32_t smem_u32(const void* p) {
    uint32_t a;
    asm("{ .reg .u64 t; cvta.to.shared.u64 t, %1; cvt.u32.u64 %0, t; }"
        : "=r"(a) : "l"(p));
    return a;
}

#define SWZ128(off) ((off) ^ (((off) >> 3) & 0x70))

__device__ __forceinline__ void cp_async16(uint32_t dst, const void* src) {
    asm volatile("cp.async.cg.shared.global [%0], [%1], 16;" :: "r"(dst), "l"(src));
}

__device__ __forceinline__ void ldsm4(uint32_t* r, uint32_t addr) {
    asm volatile("ldmatrix.sync.aligned.m8n8.x4.shared.b16 {%0,%1,%2,%3}, [%4];"
                 : "=r"(r[0]), "=r"(r[1]), "=r"(r[2]), "=r"(r[3]) : "r"(addr));
}

__device__ __forceinline__ void ldsm4t(uint32_t* r, uint32_t addr) {
    asm volatile("ldmatrix.sync.aligned.m8n8.x4.trans.shared.b16 {%0,%1,%2,%3}, [%4];"
                 : "=r"(r[0]), "=r"(r[1]), "=r"(r[2]), "=r"(r[3]) : "r"(addr));
}

__device__ __forceinline__ void mma_f16(float* d, const uint32_t* a,
                                        uint32_t b0, uint32_t b1) {
    asm volatile(
        "mma.sync.aligned.m16n8k16.row.col.f32.f16.f16.f32 "
        "{%0,%1,%2,%3}, {%4,%5,%6,%7}, {%8,%9}, {%0,%1,%2,%3};"
        : "+f"(d[0]), "+f"(d[1]), "+f"(d[2]), "+f"(d[3])
        : "r"(a[0]), "r"(a[1]), "r"(a[2]), "r"(a[3]), "r"(b0), "r"(b1));
}

// ---------------- conversion kernels ----------------------------------------
__global__ void x_split_kernel(const float* __restrict__ in,
                               __half* __restrict__ out) {
    int i = blockIdx.x * blockDim.x + threadIdx.x;
    float4 v = reinterpret_cast<const float4*>(in)[i];
    reinterpret_cast<__half2*>(out)[2 * i] =
        __half2(__float2half_rn(v.x), __float2half_rn(v.y));
    reinterpret_cast<__half2*>(out)[2 * i + 1] =
        __half2(__float2half_rn(v.z), __float2half_rn(v.w));
}

__global__ void w_conv_kernel(const float* __restrict__ in,
                              __half* __restrict__ hiT, int R, int C, float sc) {
    __shared__ float tile[32][33];
    int bx = blockIdx.x * 32;
    int by = blockIdx.y * 32;
    int tx = threadIdx.x, ty = threadIdx.y;
#pragma unroll
    for (int j = 0; j < 4; ++j)
        tile[ty + j * 8][tx] = in[(long)(by + ty + j * 8) * C + bx + tx];
    __syncthreads();
#pragma unroll
    for (int j = 0; j < 4; ++j) {
        int oc = bx + ty + j * 8;
        int orow = by + tx;
        hiT[(long)oc * R + orow] = __float2half_rn(tile[tx][ty + j * 8] * sc);
    }
}

// ---------------- GEMM1: G-partial = x^T x from NATURAL-layout x -------------
// (unchanged from R16; occ 2, grid 288 = 0.97 wave)

#define KT1 64
#define T1_TILE 16384
#define T1_STAGE (2 * T1_TILE)
#define SMEM1_TOT (3 * T1_STAGE)      // 96 KB

__global__ __launch_bounds__(256, 2) void gemm_symt(
    const __half* __restrict__ X, float* __restrict__ P,
    int Khalf, int lda, long sX)
{
    extern __shared__ __align__(1024) unsigned char smem[];
    const uint32_t sbase = smem_u32(smem);
    const int tid = threadIdx.x;
    const int wid = tid >> 5;
    const int lane = tid & 31;
    const int warp_m = wid >> 2;
    const int warp_n = wid & 3;
    const int bz = blockIdx.z;

    int bi = 0, r = blockIdx.x;
    while (r >= 8 - bi) { r -= 8 - bi; ++bi; }
    int bj = bi + r;
    const int m0 = bi * 128, n0 = bj * 128;

    const long koff = (long)blockIdx.y * Khalf;
    const __half* src = X + bz * sX + koff * lda;

    const int l = lane & 7;
    const int j = lane >> 3;
    const uint32_t lrow = (uint32_t)((((j >> 1) * 8) + l) * 128);
    const uint32_t lmask = (uint32_t)(l << 4);
    uint32_t acol[4], bcol[2];
#pragma unroll
    for (int mi = 0; mi < 4; ++mi)
        acol[mi] = ((uint32_t)((mi * 16 + (j & 1) * 8) * 2)) ^ lmask;
#pragma unroll
    for (int u = 0; u < 2; ++u)
        bcol[u] = ((uint32_t)(((warp_n & 1) * 32 + u * 16 + (j & 1) * 8) * 2)) ^ lmask;
    const uint32_t aregion = (uint32_t)warp_m * 8192;
    const uint32_t bregion = (uint32_t)(warp_n >> 1) * 8192;

    float acc[4][4][4];
#pragma unroll
    for (int i = 0; i < 4; ++i)
#pragma unroll
        for (int q = 0; q < 4; ++q)
#pragma unroll
            for (int c = 0; c < 4; ++c) acc[i][q][c] = 0.0f;

    const int T = Khalf / KT1;

    auto load_tile = [&](int p, int k0) {
        uint32_t dst0 = sbase + (uint32_t)p * T1_STAGE;
#pragma unroll
        for (int i = 0; i < 8; ++i) {
            int cid = tid + i * 256;
            int tile = cid >> 10;
            int idx = cid & 1023;
            int row = idx >> 4;
            int ck = idx & 15;
            const __half* sp = src + (long)(k0 + row) * lda
                             + (tile ? n0 : m0) + ck * 8;
            uint32_t off = (uint32_t)((ck >> 3) * 8192)
                         + SWZ128((uint32_t)(row * 128 + (ck & 7) * 16));
            cp_async16(dst0 + (uint32_t)tile * T1_TILE + off, sp);
        }
        asm volatile("cp.async.commit_group;");
    };

    load_tile(0, 0);
    if (T > 1) load_tile(1, KT1);

    for (int t = 0; t < T; ++t) {
        if (t + 1 < T) asm volatile("cp.async.wait_group 1;");
        else           asm volatile("cp.async.wait_group 0;");
        __syncthreads();
        if (t + 2 < T) load_tile((t + 2) % 3, (t + 2) * KT1);

        const uint32_t st = sbase + (uint32_t)(t % 3) * T1_STAGE;
        const uint32_t ta = st + aregion;
        const uint32_t tb = st + T1_TILE + bregion;

#pragma unroll
        for (int kk = 0; kk < KT1; kk += 16) {
            const uint32_t kbase = (uint32_t)(kk * 128) + lrow;
            uint32_t a[4][4], bf[2][4];
#pragma unroll
            for (int u = 0; u < 2; ++u)
                ldsm4t(bf[u], tb + kbase + bcol[u]);
#pragma unroll
            for (int mi = 0; mi < 4; ++mi)
                ldsm4t(a[mi], ta + kbase + acol[mi]);
#pragma unroll
            for (int mi = 0; mi < 4; ++mi)
#pragma unroll
                for (int nj = 0; nj < 4; ++nj)
                    mma_f16(acc[mi][nj], a[mi], bf[nj >> 1][nj & 1], bf[nj >> 1][2 + (nj & 1)]);
        }
    }

    const int rr = lane >> 2;
    const int cc = (lane & 3) * 2;
    float* cpart = P + ((((long)blockIdx.y * gridDim.z) + bz) * 36 + blockIdx.x) * 16384;

#pragma unroll
    for (int mi = 0; mi < 4; ++mi)
#pragma unroll
        for (int nj = 0; nj < 4; ++nj) {
            int lrow0 = warp_m * 64 + mi * 16 + rr;
            int lcol = warp_n * 32 + nj * 8 + cc;
            *reinterpret_cast<float2*>(cpart + lrow0 * 128 + lcol) =
                make_float2(acc[mi][nj][0], acc[mi][nj][1]);
            *reinterpret_cast<float2*>(cpart + (lrow0 + 8) * 128 + lcol) =
                make_float2(acc[mi][nj][2], acc[mi][nj][3]);
        }
}

// ---------------- occ-3 HMMA GEMM (GEMM2 + GEMM3) ----------------------------
// C = P0 . PB^T, CTA tile 128(M)x64(N), 8 warps 4(m)x2(n), warp tile 32x32,
// acc 32 regs -> 3 CTA/SM (24 warps/SM). KTILE=64, 3-stage cp.async.
// MODE 0: fp32 C.  MODE 1: fp16 C.

#define KTILE 64
#define A_TILE 16384                 // 128 rows * 128 B
#define B_TILE 8192                  // 64 rows * 128 B
#define STAGE_B (A_TILE + B_TILE)    // 24 KB
#define SMEM_TOT (3 * STAGE_B)       // 72 KB

template <int MODE>
__global__ __launch_bounds__(256, 3) void gemm_hmma(
    const __half* __restrict__ P0, const __half* __restrict__ PB,
    float* __restrict__ C, __half* __restrict__ Ch,
    int K, int lda, int ldb, int ldc,
    long s0, long sB, long sC, float cscale)
{
    extern __shared__ __align__(1024) unsigned char smem[];
    const uint32_t sbase = smem_u32(smem);
    const int tid = threadIdx.x;
    const int wid = tid >> 5;
    const int lane = tid & 31;
    const int warp_m = wid & 3;    // 0..3 (32 rows each)
    const int warp_n = wid >> 2;   // 0..1 (32 cols each)
    const int bz = blockIdx.z;
    const int m0 = blockIdx.y * 128;
    const int n0 = blockIdx.x * 64;

    const __half* srcA = P0 + bz * s0 + (long)m0 * lda;
    const __half* srcB = PB + bz * sB + (long)n0 * ldb;

    const int lr = lane & 7;
    const int lg = (lane >> 3) & 1;
    const int lk = (lane >> 4) & 1;
    const int arow = warp_m * 32 + lr + lg * 8;
    const int brow = warp_n * 32 + lr + lg * 8;
    const int colb0 = lk * 16;

    float acc[2][4][4];
#pragma unroll
    for (int i = 0; i < 2; ++i)
#pragma unroll
        for (int q = 0; q < 4; ++q)
#pragma unroll
            for (int c = 0; c < 4; ++c) acc[i][q][c] = 0.0f;

    const int T = K / KTILE;

    auto load_tile = [&](int p, int k0) {
        uint32_t dst0 = sbase + (uint32_t)p * STAGE_B;
#pragma unroll
        for (int i = 0; i < 6; ++i) {
            int cid = tid + i * 256;      // 0..1535
            if (cid < 1024) {
                int row = cid >> 3;
                int ck = cid & 7;
                uint32_t off = (uint32_t)(row * 128 + ck * 16);
                cp_async16(dst0 + SWZ128(off), srcA + (long)row * lda + k0 + ck * 8);
            } else {
                int idx = cid - 1024;     // 0..511
                int row = idx >> 3;
                int ck = idx & 7;
                uint32_t off = (uint32_t)(row * 128 + ck * 16);
                cp_async16(dst0 + A_TILE + SWZ128(off), srcB + (long)row * ldb + k0 + ck * 8);
            }
        }
        asm volatile("cp.async.commit_group;");
    };

    load_tile(0, 0);
    if (T > 1) load_tile(1, KTILE);

    for (int t = 0; t < T; ++t) {
        if (t + 1 < T) asm volatile("cp.async.wait_group 1;");
        else           asm volatile("cp.async.wait_group 0;");
        __syncthreads();
        if (t + 2 < T) load_tile((t + 2) % 3, (t + 2) * KTILE);

        const uint32_t st = sbase + (uint32_t)(t % 3) * STAGE_B;
        const uint32_t ta = st;
        const uint32_t tb = st + A_TILE;

#pragma unroll
        for (int kk = 0; kk < KTILE; kk += 16) {
            const int colb = colb0 + kk * 2;
            uint32_t a[2][4], bf[2][4];
#pragma unroll
            for (int q = 0; q < 2; ++q) {
                uint32_t off = (uint32_t)((brow + q * 16) * 128 + colb);
                ldsm4(bf[q], tb + SWZ128(off));
            }
#pragma unroll
            for (int mi = 0; mi < 2; ++mi) {
                uint32_t off = (uint32_t)((arow + mi * 16) * 128 + colb);
                ldsm4(a[mi], ta + SWZ128(off));
            }
#pragma unroll
            for (int mi = 0; mi < 2; ++mi)
#pragma unroll
                for (int nj = 0; nj < 4; ++nj)
                    mma_f16(acc[mi][nj], a[mi], bf[nj >> 1][nj & 1], bf[nj >> 1][2 + (nj & 1)]);
        }
    }

    const int rr = lane >> 2;
    const int cc = (lane & 3) * 2;
    const int mb = m0 + warp_m * 32;
    const int nb = n0 + warp_n * 32;

#pragma unroll
    for (int mi = 0; mi < 2; ++mi)
#pragma unroll
        for (int nj = 0; nj < 4; ++nj) {
            int row = mb + mi * 16 + rr;
            int col = nb + nj * 8 + cc;
            float d0 = acc[mi][nj][0] * cscale, d1 = acc[mi][nj][1] * cscale;
            float d2 = acc[mi][nj][2] * cscale, d3 = acc[mi][nj][3] * cscale;
            if (MODE == 0) {
                float* cp = C + bz * sC + (long)row * ldc + col;
                *reinterpret_cast<float2*>(cp) = make_float2(d0, d1);
                float* cp2 = C + bz * sC + (long)(row + 8) * ldc + col;
                *reinterpret_cast<float2*>(cp2) = make_float2(d2, d3);
            } else {
                long o0 = bz * sC + (long)row * ldc + col;
                long o1 = bz * sC + (long)(row + 8) * ldc + col;
                *reinterpret_cast<__half2*>(Ch + o0) =
                    __half2(__float2half_rn(d0), __float2half_rn(d1));
                *reinterpret_cast<__half2*>(Ch + o1) =
                    __half2(__float2half_rn(d2), __float2half_rn(d3));
            }
        }
}

// ---------------- combine: sum split-K partials, fp16, write + mirror --------
__global__ __launch_bounds__(256) void combine_g(
    const float* __restrict__ P, __half* __restrict__ G, int ldc, long sC, int B)
{
    __shared__ unsigned short tb[32 * 130];
    int t = blockIdx.x, ch = blockIdx.y, bz = blockIdx.z;
    int bi = 0, r = t;
    while (r >= 8 - bi) { r -= 8 - bi; ++bi; }
    int bj = bi + r;
    int m0 = bi * 128, n0 = bj * 128;
    int r0 = ch * 32;

    const float* A0 = P + ((long)bz * 36 + t) * 16384 + r0 * 128;
    const float* A1 = P + (((long)B + bz) * 36 + t) * 16384 + r0 * 128;
    int tid = threadIdx.x;

#pragma unroll
    for (int i = 0; i < 8; ++i) {
        int j = tid + i * 256;
        float2 a0 = reinterpret_cast<const float2*>(A0)[j];
        float2 a1 = reinterpret_cast<const float2*>(A1)[j];
        __half h0 = __float2half_rn(a0.x + a1.x);
        __half h1 = __float2half_rn(a0.y + a1.y);
        int row = j >> 6;
        int col = (j & 63) << 1;
        *reinterpret_cast<__half2*>(
            &G[bz * sC + (long)(m0 + r0 + row) * ldc + n0 + col]) = __half2(h0, h1);
        tb[row * 130 + col] = __half_as_ushort(h0);
        tb[row * 130 + col + 1] = __half_as_ushort(h1);
    }

    if (bi < bj) {
        __syncthreads();
#pragma unroll
        for (int i = 0; i < 8; ++i) {
            int j = tid + i * 256;
            int p = j >> 4;
            int q2 = (j & 15) << 1;
            __half2 hv(__ushort_as_half(tb[q2 * 130 + p]),
                       __ushort_as_half(tb[(q2 + 1) * 130 + p]));
            long o = bz * sC + (long)(n0 + p) * ldc + (m0 + r0 + q2);
            *reinterpret_cast<__half2*>(&G[o]) = hv;
        }
    }
}

// ---------------- launch -----------------------------------------------------
extern "C" void kernel_launch(void* const* d_in, const int* in_sizes, int n_in,
                              void* d_out, int out_size) {
    const float* x = (const float*)d_in[0];
    const float* W = (const float*)d_in[1];
    float* out = (float*)d_out;

    const int S = S_DIM, H = H_DIM, B = B_DIM;
    const long HH = (long)H * H, SH = (long)S * H;

    __half *xhi, *WThi, *Ghi, *MThi;
    float* Pbuf;
    cudaGetSymbolAddress((void**)&xhi, g_xhi);
    cudaGetSymbolAddress((void**)&WThi, g_WThi);
    cudaGetSymbolAddress((void**)&Ghi, g_Ghi);
    cudaGetSymbolAddress((void**)&MThi, g_MThi);
    cudaGetSymbolAddress((void**)&Pbuf, g_P);

    cudaFuncSetAttribute(gemm_hmma<0>, cudaFuncAttributeMaxDynamicSharedMemorySize, SMEM_TOT);
    cudaFuncSetAttribute(gemm_hmma<1>, cudaFuncAttributeMaxDynamicSharedMemorySize, SMEM_TOT);
    cudaFuncSetAttribute(gemm_symt, cudaFuncAttributeMaxDynamicSharedMemorySize, SMEM1_TOT);

    // conversions
    x_split_kernel<<<(B * S * H / 4 + 255) / 256, 256>>>(x, xhi);
    w_conv_kernel<<<dim3(H / 32, H / 32, 1), dim3(32, 8)>>>(W, WThi, H, H, 4096.0f);

    // GEMM1 (symmetric, split-K x2, natural-layout x via ldmatrix.trans)
    gemm_symt<<<dim3(36, 2, B), 256, SMEM1_TOT>>>(
        xhi, Pbuf, S / 2, H, SH);

    // combine partials -> G (fp16, both triangles)
    combine_g<<<dim3(36, 4, B), 256>>>(Pbuf, Ghi, H, HH, B);

    // GEMM2: MT[h][k] = G[h][.] . WT[k][.]^T ; carries W's x4096 scale
    gemm_hmma<1><<<dim3(H / 64, H / 128, B), 256, SMEM_TOT>>>(
        Ghi, WThi, nullptr, MThi,
        H, H, H, H, HH, 0L, HH, 1.0f);

    // GEMM3: out = xhi . MT^T ; undo x4096
    gemm_hmma<0><<<dim3(H / 64, S / 128, B), 256, SMEM_TOT>>>(
        xhi, MThi, out, nullptr,
        H, H, H, H, SH, HH, SH, 1.0f / 4096.0f);
}